// round 1
// baseline (speedup 1.0000x reference)
#include <cuda_runtime.h>

// out[b, o, f] = sum_t x[b, t, f] * W[f, o, t] + bias[f, o],  f < 2 (TGT)
// x: (4096, 24, 256) f32   W: (256, 24, 24) f32   bias: (256, 24) f32
// out: (4096, 24, 2) f32, flattened index i = b*48 + o*2 + f

#define B_DIM 4096
#define T_DIM 24
#define F_DIM 256
#define O_DIM 24
#define TGT   2
#define TOTAL (B_DIM * O_DIM * TGT)   // 196608
#define BLOCK 256

__global__ __launch_bounds__(BLOCK) void dlinear_kernel(
    const float* __restrict__ x,
    const float* __restrict__ W,
    const float* __restrict__ bias,
    float* __restrict__ out)
{
    // Shared: W slices for f=0,1 re-laid-out as Ws[(o*2+f)*25 + t]
    // (stride 25 is coprime with 32 banks -> conflict-free reads)
    __shared__ float Ws[O_DIM * TGT * 25];   // 48*25 = 1200 floats
    __shared__ float bs[O_DIM * TGT];        // bs[o*2+f]

    const int tid = threadIdx.x;

    // Cooperative load of W[f<2] (first 1152 floats of W, layout (f,o,t))
    #pragma unroll
    for (int j = tid; j < TGT * O_DIM * T_DIM; j += BLOCK) {
        int f = j / (O_DIM * T_DIM);
        int r = j - f * (O_DIM * T_DIM);
        int o = r / T_DIM;
        int t = r - o * T_DIM;
        Ws[(o * TGT + f) * 25 + t] = W[j];
    }
    if (tid < TGT * O_DIM) {
        int f = tid / O_DIM;
        int o = tid - f * O_DIM;
        bs[o * TGT + f] = bias[f * O_DIM + o];   // bias layout (f, o)
    }
    __syncthreads();

    const int i = blockIdx.x * BLOCK + tid;
    if (i >= TOTAL) return;

    const int b = i / (O_DIM * TGT);
    const int r = i - b * (O_DIM * TGT);      // r = o*2 + f
    const int f = r & 1;

    const float* xp = x + (size_t)b * T_DIM * F_DIM + f;

    // Batch all 24 x loads up front (independent -> high MLP)
    float xv[T_DIM];
    #pragma unroll
    for (int t = 0; t < T_DIM; t++)
        xv[t] = __ldg(xp + t * F_DIM);

    float acc = bs[r];
    #pragma unroll
    for (int t = 0; t < T_DIM; t++)
        acc = fmaf(xv[t], Ws[r * 25 + t], acc);

    out[i] = acc;
}

extern "C" void kernel_launch(void* const* d_in, const int* in_sizes, int n_in,
                              void* d_out, int out_size)
{
    const float* x    = (const float*)d_in[0];
    const float* W    = (const float*)d_in[1];
    const float* bias = (const float*)d_in[2];
    float* out = (float*)d_out;

    dim3 grid((TOTAL + BLOCK - 1) / BLOCK);
    dlinear_kernel<<<grid, BLOCK>>>(x, W, bias, out);
}

// round 2
// speedup vs baseline: 1.3029x; 1.3029x over previous
#include <cuda_runtime.h>

// out[b, o, f] = sum_t x[b, t, f] * W[f, o, t] + bias[f, o],  f < TGT=2
// x: (4096, 24, 256) f32   W: (256, 24, 24) f32   bias: (256, 24) f32
// out: (4096, 24, 2) f32 flattened as i = b*48 + o*2 + f

#define B_DIM 4096
#define T_DIM 24
#define F_DIM 256
#define O_DIM 24
#define TGT   2
#define R_DIM (O_DIM * TGT)          // 48 outputs per batch row
#define NB    16                     // batch rows per block
#define BLOCK 128
#define NLOAD (NB * T_DIM)           // 384 float2 loads per block (3/thread)
#define NOUT  (NB * R_DIM)           // 768 outputs per block (6/thread)

__global__ __launch_bounds__(BLOCK) void dlinear_kernel(
    const float* __restrict__ x,
    const float* __restrict__ W,
    const float* __restrict__ bias,
    float* __restrict__ out)
{
    __shared__ float2 xs2[NB * T_DIM];        // xs[b_l][t] = (x_f0, x_f1)
    __shared__ float  Ws[R_DIM * 25];         // Ws[(o*2+f)*25 + t], stride 25 = bank-conflict-free
    __shared__ float  bs[R_DIM];              // bs[o*2+f]

    const int tid = threadIdx.x;
    const int b0  = blockIdx.x * NB;

    // ---- Phase 1a: gather x. Every lane loads a DISTINCT 128B line (float2 at
    // front of each 1KB row) -> maximal unique-request rate into DRAM.
    const float2* __restrict__ x2 = (const float2*)x;   // element stride = 128 float2 per (b,t) row
    #pragma unroll
    for (int k = tid; k < NLOAD; k += BLOCK) {
        int b_l = k / T_DIM;
        int t   = k - b_l * T_DIM;
        // float2 index of x[b0+b_l, t, 0] = ((b0+b_l)*24 + t) * 128
        xs2[k] = __ldg(x2 + (size_t)((b0 + b_l) * T_DIM + t) * (F_DIM / 2));
    }

    // ---- Phase 1b (overlapped): stage W[f<2] and bias[f<2] (hot in L2 after wave start)
    #pragma unroll
    for (int j = tid; j < TGT * O_DIM * T_DIM; j += BLOCK) {
        int f = j / (O_DIM * T_DIM);
        int r = j - f * (O_DIM * T_DIM);
        int o = r / T_DIM;
        int t = r - o * T_DIM;
        Ws[(o * TGT + f) * 25 + t] = W[j];
    }
    if (tid < R_DIM) {
        int f = tid / O_DIM;
        int o = tid - f * O_DIM;
        bs[o * TGT + f] = bias[f * O_DIM + o];
    }
    __syncthreads();

    // ---- Phase 2: 6 outputs per thread, all operands in smem, coalesced stores
    const float* xsf = (const float*)xs2;     // xsf[b_l*48 + t*2 + f]
    float* outp = out + (size_t)b0 * R_DIM;

    #pragma unroll
    for (int u = 0; u < NOUT / BLOCK; u++) {
        int e   = u * BLOCK + tid;            // 0..767, lane-consecutive -> coalesced store
        int b_l = e / R_DIM;
        int r   = e - b_l * R_DIM;            // r = o*2 + f
        int f   = r & 1;

        const float* xrow = xsf + b_l * (T_DIM * 2) + f;
        const float* wrow = Ws + r * 25;

        float acc = bs[r];
        #pragma unroll
        for (int t = 0; t < T_DIM; t++)
            acc = fmaf(xrow[t * 2], wrow[t], acc);

        outp[e] = acc;
    }
}

extern "C" void kernel_launch(void* const* d_in, const int* in_sizes, int n_in,
                              void* d_out, int out_size)
{
    const float* x    = (const float*)d_in[0];
    const float* W    = (const float*)d_in[1];
    const float* bias = (const float*)d_in[2];
    float* out = (float*)d_out;

    dim3 grid(B_DIM / NB);   // 256 blocks
    dlinear_kernel<<<grid, BLOCK>>>(x, W, bias, out);
}

// round 3
// speedup vs baseline: 1.3092x; 1.0048x over previous
#include <cuda_runtime.h>

// out[b, o, f] = sum_t x[b, t, f] * W[f, o, t] + bias[f, o],  f < TGT=2
// x: (4096, 24, 256) f32   W: (256, 24, 24) f32   bias: (256, 24) f32
// out: (4096, 24, 2) f32 flattened as i = b*48 + o*2 + f

#define B_DIM 4096
#define T_DIM 24
#define F_DIM 256
#define O_DIM 24
#define TGT   2
#define R_DIM (O_DIM * TGT)          // 48 outputs per batch row
#define NB    8                      // batch rows per block
#define BLOCK 192                    // == NB*T_DIM -> exactly 1 gather per thread
#define NLOAD (NB * T_DIM)           // 192 float2 loads per block
#define NOUT  (NB * R_DIM)           // 384 outputs per block (2/thread)

__global__ __launch_bounds__(BLOCK) void dlinear_kernel(
    const float* __restrict__ x,
    const float* __restrict__ W,
    const float* __restrict__ bias,
    float* __restrict__ out)
{
    __shared__ float2 xs2[NLOAD];             // xs[b_l][t] = (x_f0, x_f1)
    __shared__ float  Ws[R_DIM * 25];         // Ws[(o*2+f)*25 + t], stride 25 = conflict-free
    __shared__ float  bs[R_DIM];              // bs[o*2+f]

    const int tid = threadIdx.x;
    const int b0  = blockIdx.x * NB;

    // ---- Phase 1a: gather x — exactly one float2 per thread, every lane a
    // DISTINCT 128B line (front 8B of each 1KB x row) -> max unique-request rate.
    {
        const float2* __restrict__ x2 = (const float2*)x;
        int b_l = tid / T_DIM;
        int t   = tid - b_l * T_DIM;
        xs2[tid] = __ldg(x2 + (size_t)((b0 + b_l) * T_DIM + t) * (F_DIM / 2));
    }

    // ---- Phase 1b (overlapped): stage W[f<2] and bias (L2-hot after first wave)
    #pragma unroll
    for (int j = tid; j < TGT * O_DIM * T_DIM; j += BLOCK) {
        int f = j / (O_DIM * T_DIM);
        int r = j - f * (O_DIM * T_DIM);
        int o = r / T_DIM;
        int t = r - o * T_DIM;
        Ws[(o * TGT + f) * 25 + t] = W[j];
    }
    if (tid < R_DIM) {
        int f = tid / O_DIM;
        int o = tid - f * O_DIM;
        bs[o * TGT + f] = bias[f * O_DIM + o];
    }
    __syncthreads();

    // ---- Phase 2: 2 outputs per thread, all operands in smem, coalesced stores
    const float* xsf = (const float*)xs2;     // xsf[b_l*48 + t*2 + f]
    float* outp = out + (size_t)b0 * R_DIM;

    #pragma unroll
    for (int u = 0; u < NOUT / BLOCK; u++) {
        int e   = u * BLOCK + tid;            // lane-consecutive -> coalesced store
        int b_l = e / R_DIM;
        int r   = e - b_l * R_DIM;            // r = o*2 + f
        int f   = r & 1;

        const float* xrow = xsf + b_l * (T_DIM * 2) + f;
        const float* wrow = Ws + r * 25;

        float acc = bs[r];
        #pragma unroll
        for (int t = 0; t < T_DIM; t++)
            acc = fmaf(xrow[t * 2], wrow[t], acc);

        outp[e] = acc;
    }
}

extern "C" void kernel_launch(void* const* d_in, const int* in_sizes, int n_in,
                              void* d_out, int out_size)
{
    const float* x    = (const float*)d_in[0];
    const float* W    = (const float*)d_in[1];
    const float* bias = (const float*)d_in[2];
    float* out = (float*)d_out;

    dim3 grid(B_DIM / NB);   // 512 blocks
    dlinear_kernel<<<grid, BLOCK>>>(x, W, bias, out);
}